// round 14
// baseline (speedup 1.0000x reference)
#include <cuda_runtime.h>
#include <cuda_bf16.h>
#include <cstdint>

// ---------------------------------------------------------------------------
// HierarchicalBlockShuffleLayer (R13 = R12 + alignment fix): warp-level HMMA.
// Pair p couples input/output chunks {p, 31-p}:
//   out_pair[N,64] = xn_pair[N,64] @ Wp[64,64] + bias
// Wp folds monarch (alpha*Wcol@Wrow^T) + flipped block-diagonal (R6-validated
// algebra). Precision via split bf16: x=hi+lo, W=hi+lo, 3 mma products, fp32
// accumulate. Per CTA: 128-row tile; LN stats pass; per pair: convert ->
// 48 mma.sync per warp -> smem OUT (direct cols, stride 72) -> coalesced store.
// R12's OUT column swizzle made the store-phase float4 read 8B-misaligned for
// odd qt; direct mapping is aligned and equally conflict-light.
// ---------------------------------------------------------------------------

#define THREADS 512

// prebuilt W: [p][hi/lo][64 n][72 k] bf16 (n-major, k contiguous, stride 72)
__device__ __align__(16) __nv_bfloat16 W_gm[16 * 2 * 64 * 72];

// smem byte offsets
#define S_AH   0          // 128 x 72 bf16 (A hi)
#define S_AL   18432      // 128 x 72 bf16 (A lo)
#define S_WH   36864      // 64 x 72 bf16 (W hi)
#define S_WL   46080      // 64 x 72 bf16 (W lo)
#define S_OUT  55296      // 128 x 72 f32, direct columns 0..63
#define S_GAM  92160
#define S_BET  96256
#define S_BIA  100352
#define S_MU   104448
#define S_RS   104960
#define SMEM_BYTES 105472

__device__ __forceinline__ void mma16816(float* c, const uint32_t* a,
                                         const uint32_t* b) {
    asm volatile(
        "mma.sync.aligned.m16n8k16.row.col.f32.bf16.bf16.f32 "
        "{%0,%1,%2,%3}, {%4,%5,%6,%7}, {%8,%9}, {%0,%1,%2,%3};"
        : "+f"(c[0]), "+f"(c[1]), "+f"(c[2]), "+f"(c[3])
        : "r"(a[0]), "r"(a[1]), "r"(a[2]), "r"(a[3]), "r"(b[0]), "r"(b[1]));
}

// ---------------------------------------------------------------------------
// Prep: build Wp (hi/lo split bf16), n-major [64][72].
// ---------------------------------------------------------------------------
__global__ void prep_kernel(const float* __restrict__ bw,
                            const float* __restrict__ wrow,
                            const float* __restrict__ wcol,
                            const float* __restrict__ alphap) {
    const int p = blockIdx.x;
    const float alpha = alphap[0];
    for (int e = threadIdx.x; e < 4096; e += blockDim.x) {
        const int n = e >> 6, k = e & 63;
        float wv = 0.f;
        if (n < 32) {                       // out chunk r = p, s = n
            const int s = n, r = p;
            if (k < 32) {                   // monarch: input chunk p, c = k
                float acc = 0.f;
                for (int j = 0; j < 32; j++) acc += wcol[k * 32 + j] * wrow[s * 32 + j];
                wv = alpha * acc;
            } else {                        // block: input chunk q dims
                const int off = (s < 16) ? 16 : 0;
                const int b = (k - 32) - off;
                if (b >= 0 && b < 16) {
                    const int grp = (s < 16) ? (63 - 2 * r) : (62 - 2 * r);
                    const int jj  = (s < 16) ? (15 - s) : (31 - s);
                    wv = bw[grp * 256 + b * 16 + jj];
                }
            }
        } else {                            // out chunk q = 31-p, s = n-32
            const int s = n - 32, rq = 31 - p;
            if (k >= 32) {                  // monarch: input chunk q, c = k-32
                float acc = 0.f;
                for (int j = 0; j < 32; j++) acc += wcol[(k - 32) * 32 + j] * wrow[s * 32 + j];
                wv = alpha * acc;
            } else {                        // block: input chunk p dims
                const int off = (s < 16) ? 16 : 0;
                const int b = k - off;
                if (b >= 0 && b < 16) {
                    const int grp = (s < 16) ? (63 - 2 * rq) : (62 - 2 * rq);
                    const int jj  = (s < 16) ? (15 - s) : (31 - s);
                    wv = bw[grp * 256 + b * 16 + jj];
                }
            }
        }
        const __nv_bfloat16 h  = __float2bfloat16(wv);
        const __nv_bfloat16 lo = __float2bfloat16(wv - __bfloat162float(h));
        W_gm[((p * 2 + 0) * 64 + n) * 72 + k] = h;
        W_gm[((p * 2 + 1) * 64 + n) * 72 + k] = lo;
    }
}

// ---------------------------------------------------------------------------
__global__ void __launch_bounds__(THREADS, 1)
hbsl_mma_kernel(const float* __restrict__ x,
                const float* __restrict__ gamma,
                const float* __restrict__ beta,
                const float* __restrict__ bias,
                float* __restrict__ out) {
    extern __shared__ char sm[];
    uint32_t* AH32 = (uint32_t*)(sm + S_AH);
    uint32_t* AL32 = (uint32_t*)(sm + S_AL);
    uint32_t* WH32 = (uint32_t*)(sm + S_WH);
    uint32_t* WL32 = (uint32_t*)(sm + S_WL);
    float* OUT = (float*)(sm + S_OUT);
    float* GAM = (float*)(sm + S_GAM);
    float* BET = (float*)(sm + S_BET);
    float* BIA = (float*)(sm + S_BIA);
    float* MU  = (float*)(sm + S_MU);
    float* RS  = (float*)(sm + S_RS);

    const int t = threadIdx.x;
    const int w = t >> 5, l = t & 31;
    const size_t tbase = (size_t)blockIdx.x * 131072;   // 128 rows * 1024

    // stage gamma/beta/bias
    for (int i = t; i < 1024; i += THREADS) {
        GAM[i] = __ldg(gamma + i); BET[i] = __ldg(beta + i); BIA[i] = __ldg(bias + i);
    }

    // ---- pass 1: LN stats (warp w -> rows 8w..8w+7), coalesced DRAM read ----
    {
        const float4* x4 = (const float4*)(x + tbase);
#pragma unroll 1
        for (int rr = 0; rr < 8; rr++) {
            const int row = 8 * w + rr;
            const float4* rp = x4 + (size_t)row * 256;
            float s = 0.f, sq = 0.f;
#pragma unroll
            for (int j = 0; j < 8; j++) {
                const float4 v = __ldg(rp + l + 32 * j);
                s  += v.x + v.y + v.z + v.w;
                sq += v.x * v.x + v.y * v.y + v.z * v.z + v.w * v.w;
            }
#pragma unroll
            for (int o = 16; o > 0; o >>= 1) {
                s  += __shfl_xor_sync(~0u, s,  o);
                sq += __shfl_xor_sync(~0u, sq, o);
            }
            if (l == 0) {
                const float mu = s * (1.f / 1024.f);
                MU[row] = mu;
                RS[row] = rsqrtf(sq * (1.f / 1024.f) - mu * mu + 1e-5f);
            }
        }
    }
    __syncthreads();

    const int m = t >> 2, qt = t & 3;          // convert/store roles
    const int gi = l >> 2, tig = l & 3;        // mma fragment roles
    const int rb = w & 7, nh = w >> 3;         // rowblock, n-half

    // ---- per-pair loop ----
    for (int p = 0; p < 16; p++) {
        const int q = 31 - p;
        const int dimb = (qt < 2) ? 32 * p + 16 * qt : 32 * q + 16 * (qt - 2);

        // stage W_p (hi+lo, contiguous 18432 B)
        {
            const uint4* wsrc = (const uint4*)W_gm + (size_t)p * 1152;
            uint4* wdst = (uint4*)(sm + S_WH);
            for (int i = t; i < 1152; i += THREADS) wdst[i] = __ldg(wsrc + i);
        }

        // convert: thread -> (row m, 16 k-dims), LN + split bf16
        {
            const float* xr = x + tbase + (size_t)m * 1024 + dimb;
            const float mu = MU[m], rs = RS[m];
            uint32_t hw[8], lw[8];
#pragma unroll
            for (int ii = 0; ii < 4; ii++) {
                const float4 v = __ldg((const float4*)xr + ii);
                const float* gp = GAM + dimb + 4 * ii;
                const float* bp = BET + dimb + 4 * ii;
                float xs[4];
                xs[0] = (v.x - mu) * rs * gp[0] + bp[0];
                xs[1] = (v.y - mu) * rs * gp[1] + bp[1];
                xs[2] = (v.z - mu) * rs * gp[2] + bp[2];
                xs[3] = (v.w - mu) * rs * gp[3] + bp[3];
#pragma unroll
                for (int c2 = 0; c2 < 2; c2++) {
                    const __nv_bfloat16 h0 = __float2bfloat16(xs[2 * c2]);
                    const __nv_bfloat16 h1 = __float2bfloat16(xs[2 * c2 + 1]);
                    const __nv_bfloat16 e0 = __float2bfloat16(xs[2 * c2]     - __bfloat162float(h0));
                    const __nv_bfloat16 e1 = __float2bfloat16(xs[2 * c2 + 1] - __bfloat162float(h1));
                    __nv_bfloat162 hh = __halves2bfloat162(h0, h1);
                    __nv_bfloat162 ee = __halves2bfloat162(e0, e1);
                    hw[ii * 2 + c2] = *(uint32_t*)&hh;
                    lw[ii * 2 + c2] = *(uint32_t*)&ee;
                }
            }
            const int wi = m * 36 + qt * 8;       // uint32 index, stride 72 bf16
            *(uint4*)(AH32 + wi)     = make_uint4(hw[0], hw[1], hw[2], hw[3]);
            *(uint4*)(AH32 + wi + 4) = make_uint4(hw[4], hw[5], hw[6], hw[7]);
            *(uint4*)(AL32 + wi)     = make_uint4(lw[0], lw[1], lw[2], lw[3]);
            *(uint4*)(AL32 + wi + 4) = make_uint4(lw[4], lw[5], lw[6], lw[7]);
        }
        __syncthreads();

        // ---- mma: warp = (rowblock rb, n-half nh); 4 k-steps x 4 n-steps ----
        {
            float acc[4][4] = {};
            const int arow = (rb * 16 + gi) * 36 + tig;
#pragma unroll
            for (int ks = 0; ks < 4; ks++) {
                uint32_t ahi[4], alo[4];
                const int ai = arow + ks * 8;
                ahi[0] = AH32[ai];           ahi[1] = AH32[ai + 288];
                ahi[2] = AH32[ai + 4];       ahi[3] = AH32[ai + 292];
                alo[0] = AL32[ai];           alo[1] = AL32[ai + 288];
                alo[2] = AL32[ai + 4];       alo[3] = AL32[ai + 292];
#pragma unroll
                for (int nb = 0; nb < 4; nb++) {
                    const int bi = (nh * 32 + nb * 8 + gi) * 36 + ks * 8 + tig;
                    uint32_t bh[2], bl[2];
                    bh[0] = WH32[bi]; bh[1] = WH32[bi + 4];
                    bl[0] = WL32[bi]; bl[1] = WL32[bi + 4];
                    mma16816(acc[nb], ahi, bh);
                    mma16816(acc[nb], ahi, bl);
                    mma16816(acc[nb], alo, bh);
                }
            }
            // epilogue: D frags -> OUT (direct columns, stride 72)
            const int row0 = rb * 16 + gi;
#pragma unroll
            for (int nb = 0; nb < 4; nb++) {
                const int col = nh * 32 + nb * 8 + tig * 2;
                *(float2*)(OUT + row0 * 72 + col)       = make_float2(acc[nb][0], acc[nb][1]);
                *(float2*)(OUT + (row0 + 8) * 72 + col) = make_float2(acc[nb][2], acc[nb][3]);
            }
        }
        __syncthreads();

        // ---- store: thread -> (row m, 16 out-dims), coalesced STG + bias ----
        {
            const float* ob = OUT + m * 72 + qt * 16;       // 16B-aligned
            float* og = out + tbase + (size_t)m * 1024 + dimb;
#pragma unroll
            for (int ii = 0; ii < 4; ii++) {
                const float4 dv = *(const float4*)(ob + 4 * ii);
                float4 vv;
                vv.x = dv.x + BIA[dimb + 4 * ii + 0];
                vv.y = dv.y + BIA[dimb + 4 * ii + 1];
                vv.z = dv.z + BIA[dimb + 4 * ii + 2];
                vv.w = dv.w + BIA[dimb + 4 * ii + 3];
                *(float4*)(og + 4 * ii) = vv;
            }
        }
        __syncthreads();   // OUT/A reused next pair
    }
}

// ---------------------------------------------------------------------------
extern "C" void kernel_launch(void* const* d_in, const int* in_sizes, int n_in,
                              void* d_out, int out_size) {
    const float* x     = (const float*)d_in[0];
    const float* gamma = (const float*)d_in[1];
    const float* beta  = (const float*)d_in[2];
    const float* bw    = (const float*)d_in[3];
    const float* wrow  = (const float*)d_in[4];
    const float* wcol  = (const float*)d_in[5];
    const float* alpha = (const float*)d_in[6];
    const float* bias  = (const float*)d_in[7];
    float* out = (float*)d_out;

    const int rows = in_sizes[0] / 1024;
    const int ntiles = rows / 128;             // 256 for the bench shape

    prep_kernel<<<16, 256>>>(bw, wrow, wcol, alpha);

    cudaFuncSetAttribute(hbsl_mma_kernel,
                         cudaFuncAttributeMaxDynamicSharedMemorySize, SMEM_BYTES);
    hbsl_mma_kernel<<<ntiles, THREADS, SMEM_BYTES>>>(x, gamma, beta, bias, out);
}

// round 15
// speedup vs baseline: 1.3189x; 1.3189x over previous
#include <cuda_runtime.h>
#include <cuda_bf16.h>
#include <cstdint>

// ---------------------------------------------------------------------------
// HierarchicalBlockShuffleLayer (R14): single fused HMMA kernel.
//   out_pair_p[128,64] = xn_pair_p[128,64] @ Wp[64,64] + bias,  p = 0..15
// Wp folds monarch (alpha*Wcol@Wrow^T) + flipped block-diag (R13-validated).
// Split bf16 (x=hi+lo, W=hi+lo, 3 mma products, fp32 accum).
// vs R13: no prep kernel (M + Wp built in-CTA), no OUT smem (direct fragment
// STG with bias), 2 barriers/pair, 2 CTAs/SM (smem 72.7KB, 64 regs).
// ---------------------------------------------------------------------------

#define THREADS 512

// smem byte offsets
#define S_AH   0          // 128 x 72 bf16 (A hi)
#define S_AL   18432      // 128 x 72 bf16 (A lo)
#define S_WH   36864      // 64 x 72 bf16 (W hi)
#define S_WL   46080      // 64 x 72 bf16 (W lo)
#define S_M    55296      // 32 x 32 f32 (alpha-folded monarch)
#define S_GAM  59392
#define S_BET  63488
#define S_BIA  67584
#define S_MU   71680
#define S_RS   72192
#define SMEM_BYTES 72704

__device__ __forceinline__ void mma16816(float* c, const uint32_t* a,
                                         const uint32_t* b) {
    asm volatile(
        "mma.sync.aligned.m16n8k16.row.col.f32.bf16.bf16.f32 "
        "{%0,%1,%2,%3}, {%4,%5,%6,%7}, {%8,%9}, {%0,%1,%2,%3};"
        : "+f"(c[0]), "+f"(c[1]), "+f"(c[2]), "+f"(c[3])
        : "r"(a[0]), "r"(a[1]), "r"(a[2]), "r"(a[3]), "r"(b[0]), "r"(b[1]));
}

__global__ void __launch_bounds__(THREADS, 2)
hbsl_mma_kernel(const float* __restrict__ x,
                const float* __restrict__ gamma,
                const float* __restrict__ beta,
                const float* __restrict__ bw,
                const float* __restrict__ wrow,
                const float* __restrict__ wcol,
                const float* __restrict__ alphap,
                const float* __restrict__ bias,
                float* __restrict__ out) {
    extern __shared__ char sm[];
    uint32_t* AH32 = (uint32_t*)(sm + S_AH);
    uint32_t* AL32 = (uint32_t*)(sm + S_AL);
    uint32_t* WH32 = (uint32_t*)(sm + S_WH);
    uint32_t* WL32 = (uint32_t*)(sm + S_WL);
    float* Msm = (float*)(sm + S_M);
    float* GAM = (float*)(sm + S_GAM);
    float* BET = (float*)(sm + S_BET);
    float* BIA = (float*)(sm + S_BIA);
    float* MU  = (float*)(sm + S_MU);
    float* RS  = (float*)(sm + S_RS);

    const int t = threadIdx.x;
    const int w = t >> 5, l = t & 31;
    const size_t tbase = (size_t)blockIdx.x * 131072;   // 128 rows * 1024

    // stage gamma/beta/bias
    for (int i = t; i < 1024; i += THREADS) {
        GAM[i] = __ldg(gamma + i); BET[i] = __ldg(beta + i); BIA[i] = __ldg(bias + i);
    }
    // build alpha-folded monarch M[k][s] (2 entries/thread)
    {
        const float alpha = __ldg(alphap);
#pragma unroll
        for (int u = 0; u < 2; u++) {
            const int id = t + 512 * u;
            const int c = id >> 5, s = id & 31;
            float acc = 0.f;
#pragma unroll
            for (int j = 0; j < 32; j++)
                acc += __ldg(wcol + c * 32 + j) * __ldg(wrow + s * 32 + j);
            Msm[id] = alpha * acc;
        }
    }

    // ---- pass 1: LN stats (warp w -> rows 8w..8w+7), coalesced DRAM read ----
    {
        const float4* x4 = (const float4*)(x + tbase);
#pragma unroll 1
        for (int rr = 0; rr < 8; rr++) {
            const int row = 8 * w + rr;
            const float4* rp = x4 + (size_t)row * 256;
            float s = 0.f, sq = 0.f;
#pragma unroll
            for (int j = 0; j < 8; j++) {
                const float4 v = __ldg(rp + l + 32 * j);
                s  += v.x + v.y + v.z + v.w;
                sq += v.x * v.x + v.y * v.y + v.z * v.z + v.w * v.w;
            }
#pragma unroll
            for (int o = 16; o > 0; o >>= 1) {
                s  += __shfl_xor_sync(~0u, s,  o);
                sq += __shfl_xor_sync(~0u, sq, o);
            }
            if (l == 0) {
                const float mu = s * (1.f / 1024.f);
                MU[row] = mu;
                RS[row] = rsqrtf(sq * (1.f / 1024.f) - mu * mu + 1e-5f);
            }
        }
    }
    __syncthreads();

    const int m = t >> 2, qt = t & 3;          // convert roles
    const int gi = l >> 2, tig = l & 3;        // mma fragment roles
    const int rb = w & 7, nh = w >> 3;         // rowblock, n-half

    // W-build role: thread -> row n = t>>3, k-dims 8*(t&7)..+7
    const int wn = t >> 3, wk0 = (t & 7) * 8;

    // ---- per-pair loop ----
    for (int p = 0; p < 16; p++) {
        const int q = 31 - p;

        // build W_p hi/lo in smem: 8 entries/thread
        {
            const int n = wn;
            const int s = (n < 32) ? n : (n - 32);
            const int off = (s < 16) ? 16 : 0;
            const int jj  = (s < 16) ? (15 - s) : (31 - s);
            const int rr  = (n < 32) ? p : q;
            const int grp = (s < 16) ? (63 - 2 * rr) : (62 - 2 * rr);
            uint32_t hw[4], lw[4];
#pragma unroll
            for (int i2 = 0; i2 < 4; i2++) {
                float wv2[2];
#pragma unroll
                for (int j2 = 0; j2 < 2; j2++) {
                    const int k = wk0 + i2 * 2 + j2;
                    float wv = 0.f;
                    const bool mon = (n < 32) ? (k < 32) : (k >= 32);
                    if (mon) {
                        const int c = (n < 32) ? k : (k - 32);
                        wv = Msm[c * 32 + s];
                    } else {
                        const int kk = (n < 32) ? (k - 32) : k;
                        const int b = kk - off;
                        if (b >= 0 && b < 16)
                            wv = __ldg(bw + grp * 256 + b * 16 + jj);
                    }
                    wv2[j2] = wv;
                }
                const __nv_bfloat16 h0 = __float2bfloat16(wv2[0]);
                const __nv_bfloat16 h1 = __float2bfloat16(wv2[1]);
                const __nv_bfloat16 e0 = __float2bfloat16(wv2[0] - __bfloat162float(h0));
                const __nv_bfloat16 e1 = __float2bfloat16(wv2[1] - __bfloat162float(h1));
                __nv_bfloat162 hh = __halves2bfloat162(h0, h1);
                __nv_bfloat162 ee = __halves2bfloat162(e0, e1);
                hw[i2] = *(uint32_t*)&hh;
                lw[i2] = *(uint32_t*)&ee;
            }
            const int wi = wn * 36 + wk0 / 2;        // uint32 index, stride 72 bf16
            *(uint4*)(WH32 + wi) = make_uint4(hw[0], hw[1], hw[2], hw[3]);
            *(uint4*)(WL32 + wi) = make_uint4(lw[0], lw[1], lw[2], lw[3]);
        }

        // convert A: thread -> (row m, 16 k-dims), LN + split bf16
        {
            const int dimb = (qt < 2) ? 32 * p + 16 * qt : 32 * q + 16 * (qt - 2);
            const float* xr = x + tbase + (size_t)m * 1024 + dimb;
            const float mu = MU[m], rs = RS[m];
            uint32_t hw[8], lw[8];
#pragma unroll
            for (int ii = 0; ii < 4; ii++) {
                const float4 v = __ldg((const float4*)xr + ii);
                const float* gp = GAM + dimb + 4 * ii;
                const float* bp = BET + dimb + 4 * ii;
                float xs[4];
                xs[0] = (v.x - mu) * rs * gp[0] + bp[0];
                xs[1] = (v.y - mu) * rs * gp[1] + bp[1];
                xs[2] = (v.z - mu) * rs * gp[2] + bp[2];
                xs[3] = (v.w - mu) * rs * gp[3] + bp[3];
#pragma unroll
                for (int c2 = 0; c2 < 2; c2++) {
                    const __nv_bfloat16 h0 = __float2bfloat16(xs[2 * c2]);
                    const __nv_bfloat16 h1 = __float2bfloat16(xs[2 * c2 + 1]);
                    const __nv_bfloat16 e0 = __float2bfloat16(xs[2 * c2]     - __bfloat162float(h0));
                    const __nv_bfloat16 e1 = __float2bfloat16(xs[2 * c2 + 1] - __bfloat162float(h1));
                    __nv_bfloat162 hh = __halves2bfloat162(h0, h1);
                    __nv_bfloat162 ee = __halves2bfloat162(e0, e1);
                    hw[ii * 2 + c2] = *(uint32_t*)&hh;
                    lw[ii * 2 + c2] = *(uint32_t*)&ee;
                }
            }
            const int wi = m * 36 + qt * 8;
            *(uint4*)(AH32 + wi)     = make_uint4(hw[0], hw[1], hw[2], hw[3]);
            *(uint4*)(AH32 + wi + 4) = make_uint4(hw[4], hw[5], hw[6], hw[7]);
            *(uint4*)(AL32 + wi)     = make_uint4(lw[0], lw[1], lw[2], lw[3]);
            *(uint4*)(AL32 + wi + 4) = make_uint4(lw[4], lw[5], lw[6], lw[7]);
        }
        __syncthreads();

        // ---- mma + direct store: warp = (rowblock rb, n-half nh) ----
        {
            float acc[4][4] = {};
            const int arow = (rb * 16 + gi) * 36 + tig;
#pragma unroll
            for (int ks = 0; ks < 4; ks++) {
                uint32_t ahi[4], alo[4];
                const int ai = arow + ks * 8;
                ahi[0] = AH32[ai];           ahi[1] = AH32[ai + 288];
                ahi[2] = AH32[ai + 4];       ahi[3] = AH32[ai + 292];
                alo[0] = AL32[ai];           alo[1] = AL32[ai + 288];
                alo[2] = AL32[ai + 4];       alo[3] = AL32[ai + 292];
#pragma unroll
                for (int nb = 0; nb < 4; nb++) {
                    const int bi = (nh * 32 + nb * 8 + gi) * 36 + ks * 8 + tig;
                    uint32_t bh[2], bl[2];
                    bh[0] = WH32[bi]; bh[1] = WH32[bi + 4];
                    bl[0] = WL32[bi]; bl[1] = WL32[bi + 4];
                    mma16816(acc[nb], ahi, bh);
                    mma16816(acc[nb], ahi, bl);
                    mma16816(acc[nb], alo, bh);
                }
            }
            // direct store with bias: quad covers a full 32B sector
            const int chunkb = nh ? 32 * q : 32 * p;
            const int row0 = rb * 16 + gi;
            float* ob0 = out + tbase + (size_t)row0 * 1024 + chunkb;
            float* ob1 = ob0 + 8 * 1024;
#pragma unroll
            for (int nb = 0; nb < 4; nb++) {
                const int cc = nb * 8 + tig * 2;
                const float2 bb = *(const float2*)(BIA + chunkb + cc);
                *(float2*)(ob0 + cc) = make_float2(acc[nb][0] + bb.x, acc[nb][1] + bb.y);
                *(float2*)(ob1 + cc) = make_float2(acc[nb][2] + bb.x, acc[nb][3] + bb.y);
            }
        }
        __syncthreads();   // A/W reused next pair
    }
}

// ---------------------------------------------------------------------------
extern "C" void kernel_launch(void* const* d_in, const int* in_sizes, int n_in,
                              void* d_out, int out_size) {
    const float* x     = (const float*)d_in[0];
    const float* gamma = (const float*)d_in[1];
    const float* beta  = (const float*)d_in[2];
    const float* bw    = (const float*)d_in[3];
    const float* wrow  = (const float*)d_in[4];
    const float* wcol  = (const float*)d_in[5];
    const float* alpha = (const float*)d_in[6];
    const float* bias  = (const float*)d_in[7];
    float* out = (float*)d_out;

    const int rows = in_sizes[0] / 1024;
    const int ntiles = rows / 128;             // 256 for the bench shape

    cudaFuncSetAttribute(hbsl_mma_kernel,
                         cudaFuncAttributeMaxDynamicSharedMemorySize, SMEM_BYTES);
    hbsl_mma_kernel<<<ntiles, THREADS, SMEM_BYTES>>>(x, gamma, beta, bw, wrow,
                                                     wcol, alpha, bias, out);
}